// round 1
// baseline (speedup 1.0000x reference)
#include <cuda_runtime.h>

// ---------------------------------------------------------------------------
// HeteroGraphSAGE forward on GB300.
//   xi = x_issue @ W_mlp^T + b_mlp
//   agg_i[dst[e]] += x_user[src[e]]          agg_u[src[e]] += xi[dst[e]]
//   h_i = relu(agg_i@c1uiRel^T + b + xi@c1uiRoot^T)
//   h_u = relu(agg_u@c1iuRel^T + b + x_user@c1iuRoot^T)
//   agg2_i[dst[e]] += h_u[src[e]]            agg2_u[src[e]] += h_i[dst[e]]
//   out_issue = agg2_i@c2uiRel^T + b + h_i@c2uiRoot^T
//   out_user  = agg2_u@c2iuRel^T + b + h_u@c2iuRoot^T
// ---------------------------------------------------------------------------

#define NU   100000
#define NI   200000
#define NE   600000
#define DIN  128
#define DHID 256
#define DOUT 128

// scratch layout (floats)
#define OFF_XI      0LL
#define OFF_AGG_I   25600000LL
#define OFF_AGG_U   51200000LL
#define OFF_H_I     64000000LL
#define OFF_H_U     115200000LL
#define OFF_AGG2_I  140800000LL
#define OFF_AGG2_U  192000000LL
#define SCRATCH_SZ  217600000LL

__device__ float g_scratch[SCRATCH_SZ];

// ---------------------------------------------------------------------------
// Fused GEMM: C[M,N] = A1[M,K]@W1[N,K]^T + bias[N] (+ A2[M,K]@W2[N,K]^T), opt relu
// Tile 128x128, BK=16, 256 threads, 8x8 per thread.
// ---------------------------------------------------------------------------
#define BM 128
#define BN 128
#define BK 16

__global__ void __launch_bounds__(256, 2) gemm_fused_kernel(
    const float* __restrict__ A1, const float* __restrict__ W1,
    const float* __restrict__ bias,
    const float* __restrict__ A2, const float* __restrict__ W2,
    float* __restrict__ C, int M, int N, int K, int do_relu)
{
    __shared__ float As[BK][BM];
    __shared__ float Ws[BK][BN];

    const int bm = blockIdx.y * BM;
    const int bn = blockIdx.x * BN;
    const int tid = threadIdx.x;
    const int tx = tid & 15;        // 0..15 -> n
    const int ty = tid >> 4;        // 0..15 -> m

    float acc[8][8];
#pragma unroll
    for (int i = 0; i < 8; i++)
#pragma unroll
        for (int j = 0; j < 8; j++) acc[i][j] = 0.0f;

    const int npass = (A2 != nullptr) ? 2 : 1;

    for (int pass = 0; pass < npass; pass++) {
        const float* __restrict__ A = pass ? A2 : A1;
        const float* __restrict__ W = pass ? W2 : W1;

        for (int k0 = 0; k0 < K; k0 += BK) {
            // Load A tile (128 rows x 16 k) -> As[k][m], transposed stores
#pragma unroll
            for (int i = 0; i < 2; i++) {
                int t   = tid + i * 256;     // 0..511
                int row = t >> 2;            // 0..127
                int c4  = (t & 3) * 4;       // 0,4,8,12
                float4 v = make_float4(0.f, 0.f, 0.f, 0.f);
                int gr = bm + row;
                if (gr < M)
                    v = *(const float4*)(A + (size_t)gr * K + k0 + c4);
                As[c4 + 0][row] = v.x;
                As[c4 + 1][row] = v.y;
                As[c4 + 2][row] = v.z;
                As[c4 + 3][row] = v.w;
            }
            // Load W tile (128 n-rows x 16 k) -> Ws[k][n]  (N is multiple of 128)
#pragma unroll
            for (int i = 0; i < 2; i++) {
                int t   = tid + i * 256;
                int row = t >> 2;
                int c4  = (t & 3) * 4;
                float4 v = *(const float4*)(W + (size_t)(bn + row) * K + k0 + c4);
                Ws[c4 + 0][row] = v.x;
                Ws[c4 + 1][row] = v.y;
                Ws[c4 + 2][row] = v.z;
                Ws[c4 + 3][row] = v.w;
            }
            __syncthreads();

#pragma unroll
            for (int k = 0; k < BK; k++) {
                float ra[8], rb[8];
                *(float4*)(ra)     = *(const float4*)&As[k][ty * 8];
                *(float4*)(ra + 4) = *(const float4*)&As[k][ty * 8 + 4];
                *(float4*)(rb)     = *(const float4*)&Ws[k][tx * 8];
                *(float4*)(rb + 4) = *(const float4*)&Ws[k][tx * 8 + 4];
#pragma unroll
                for (int i = 0; i < 8; i++)
#pragma unroll
                    for (int j = 0; j < 8; j++)
                        acc[i][j] += ra[i] * rb[j];
            }
            __syncthreads();
        }
    }

    // epilogue: bias + optional relu
    float bv[8];
#pragma unroll
    for (int j = 0; j < 8; j++) bv[j] = bias[bn + tx * 8 + j];

#pragma unroll
    for (int i = 0; i < 8; i++) {
        int gr = bm + ty * 8 + i;
        if (gr >= M) continue;
        float* crow = C + (size_t)gr * N + bn + tx * 8;
#pragma unroll
        for (int j = 0; j < 8; j += 4) {
            float4 v;
            v.x = acc[i][j + 0] + bv[j + 0];
            v.y = acc[i][j + 1] + bv[j + 1];
            v.z = acc[i][j + 2] + bv[j + 2];
            v.w = acc[i][j + 3] + bv[j + 3];
            if (do_relu) {
                v.x = fmaxf(v.x, 0.f); v.y = fmaxf(v.y, 0.f);
                v.z = fmaxf(v.z, 0.f); v.w = fmaxf(v.w, 0.f);
            }
            *(float4*)(crow + j) = v;
        }
    }
}

// ---------------------------------------------------------------------------
// Edge scatter-add:  agg[sidx[e]] += x[gidx[e]]   (F floats per row)
// One thread per (edge, float4 chunk).
// ---------------------------------------------------------------------------
__global__ void scatter_add_kernel(const float* __restrict__ x,
                                   const int* __restrict__ gidx,
                                   const int* __restrict__ sidx,
                                   float* __restrict__ agg,
                                   int E, int F)
{
    const int chunks = F >> 2;
    long long idx = (long long)blockIdx.x * blockDim.x + threadIdx.x;
    long long total = (long long)E * chunks;
    if (idx >= total) return;
    int e = (int)(idx / chunks);
    int c = (int)(idx - (long long)e * chunks) * 4;

    int g = __ldg(gidx + e);
    int s = __ldg(sidx + e);
    float4 v = *(const float4*)(x + (size_t)g * F + c);
    float* p = agg + (size_t)s * F + c;
    atomicAdd(p + 0, v.x);
    atomicAdd(p + 1, v.y);
    atomicAdd(p + 2, v.z);
    atomicAdd(p + 3, v.w);
}

// ---------------------------------------------------------------------------

static inline dim3 gemm_grid(int M, int N) {
    return dim3(N / 128, (M + 127) / 128);
}

extern "C" void kernel_launch(void* const* d_in, const int* in_sizes, int n_in,
                              void* d_out, int out_size)
{
    const float* x_user       = (const float*)d_in[0];
    const float* x_issue      = (const float*)d_in[1];
    const float* W_mlp        = (const float*)d_in[2];
    const float* b_mlp        = (const float*)d_in[3];
    const float* c1_ui_rel_W  = (const float*)d_in[4];
    const float* c1_ui_rel_b  = (const float*)d_in[5];
    const float* c1_ui_root_W = (const float*)d_in[6];
    const float* c1_iu_rel_W  = (const float*)d_in[7];
    const float* c1_iu_rel_b  = (const float*)d_in[8];
    const float* c1_iu_root_W = (const float*)d_in[9];
    const float* c2_ui_rel_W  = (const float*)d_in[10];
    const float* c2_ui_rel_b  = (const float*)d_in[11];
    const float* c2_ui_root_W = (const float*)d_in[12];
    const float* c2_iu_rel_W  = (const float*)d_in[13];
    const float* c2_iu_rel_b  = (const float*)d_in[14];
    const float* c2_iu_root_W = (const float*)d_in[15];
    const int*   src          = (const int*)d_in[16];  // user index per edge
    const int*   dst          = (const int*)d_in[17];  // issue index per edge

    float* out       = (float*)d_out;
    float* out_issue = out;
    float* out_user  = out + (size_t)NI * DOUT;

    float* S = nullptr;
    cudaGetSymbolAddress((void**)&S, g_scratch);
    float* xi     = S + OFF_XI;
    float* agg_i  = S + OFF_AGG_I;
    float* agg_u  = S + OFF_AGG_U;
    float* h_i    = S + OFF_H_I;
    float* h_u    = S + OFF_H_U;
    float* agg2_i = S + OFF_AGG2_I;
    float* agg2_u = S + OFF_AGG2_U;

    // zero aggregation buffers
    cudaMemsetAsync(agg_i,  0, (size_t)NI * DIN  * sizeof(float), 0);
    cudaMemsetAsync(agg_u,  0, (size_t)NU * DIN  * sizeof(float), 0);
    cudaMemsetAsync(agg2_i, 0, (size_t)NI * DHID * sizeof(float), 0);
    cudaMemsetAsync(agg2_u, 0, (size_t)NU * DHID * sizeof(float), 0);

    dim3 blk(256);

    // xi = x_issue @ W_mlp^T + b_mlp
    gemm_fused_kernel<<<gemm_grid(NI, DIN), blk>>>(
        x_issue, W_mlp, b_mlp, nullptr, nullptr, xi, NI, DIN, DIN, 0);

    // conv1 scatters (F = 128)
    {
        long long tot = (long long)NE * (DIN / 4);
        int nb = (int)((tot + 255) / 256);
        // agg_i[dst[e]] += x_user[src[e]]
        scatter_add_kernel<<<nb, blk>>>(x_user, src, dst, agg_i, NE, DIN);
        // agg_u[src[e]] += xi[dst[e]]
        scatter_add_kernel<<<nb, blk>>>(xi, dst, src, agg_u, NE, DIN);
    }

    // h_i = relu(agg_i@c1_ui_rel^T + b + xi@c1_ui_root^T)   (M=NI, N=256, K=128)
    gemm_fused_kernel<<<gemm_grid(NI, DHID), blk>>>(
        agg_i, c1_ui_rel_W, c1_ui_rel_b, xi, c1_ui_root_W, h_i, NI, DHID, DIN, 1);
    // h_u = relu(agg_u@c1_iu_rel^T + b + x_user@c1_iu_root^T)
    gemm_fused_kernel<<<gemm_grid(NU, DHID), blk>>>(
        agg_u, c1_iu_rel_W, c1_iu_rel_b, x_user, c1_iu_root_W, h_u, NU, DHID, DIN, 1);

    // conv2 scatters (F = 256)
    {
        long long tot = (long long)NE * (DHID / 4);
        int nb = (int)((tot + 255) / 256);
        // agg2_i[dst[e]] += h_u[src[e]]
        scatter_add_kernel<<<nb, blk>>>(h_u, src, dst, agg2_i, NE, DHID);
        // agg2_u[src[e]] += h_i[dst[e]]
        scatter_add_kernel<<<nb, blk>>>(h_i, dst, src, agg2_u, NE, DHID);
    }

    // out_issue = agg2_i@c2_ui_rel^T + b + h_i@c2_ui_root^T  (M=NI, N=128, K=256)
    gemm_fused_kernel<<<gemm_grid(NI, DOUT), blk>>>(
        agg2_i, c2_ui_rel_W, c2_ui_rel_b, h_i, c2_ui_root_W, out_issue, NI, DOUT, DHID, 0);
    // out_user = agg2_u@c2_iu_rel^T + b + h_u@c2_iu_root^T
    gemm_fused_kernel<<<gemm_grid(NU, DOUT), blk>>>(
        agg2_u, c2_iu_rel_W, c2_iu_rel_b, h_u, c2_iu_root_W, out_user, NU, DOUT, DHID, 0);
}

// round 4
// speedup vs baseline: 1.3153x; 1.3153x over previous
#include <cuda_runtime.h>

// ---------------------------------------------------------------------------
// HeteroGraphSAGE forward on GB300 — round 2.
//   xi = x_issue @ W_mlp^T + b_mlp
//   agg_i[dst[e]] += x_user[src[e]]       agg_u[src[e]] += xi[dst[e]]
//   h_i = relu(agg_i@c1uiRel^T + b + xi@c1uiRoot^T)
//   h_u = relu(agg_u@c1iuRel^T + b + x_user@c1iuRoot^T)
//   // conv2 rewritten: lin_rel(segsum(x)) == segsum(lin_rel(x))
//   y_u2 = h_u @ c2uiRel^T ; y_i2 = h_i @ c2iuRel^T      (128-dim)
//   agg2_i[dst[e]] += y_u2[src[e]] ; agg2_u[src[e]] += y_i2[dst[e]]
//   out_issue = h_i@c2uiRoot^T + c2ui_b + agg2_i
//   out_user  = h_u@c2iuRoot^T + c2iu_b + agg2_u
// ---------------------------------------------------------------------------

#define NU   100000
#define NI   200000
#define NE   600000
#define DIN  128
#define DHID 256
#define DOUT 128

// scratch layout (floats)
#define OFF_XI      0LL          // NI*128 = 25.6M
#define OFF_AGG_I   25600000LL   // NI*128
#define OFF_AGG_U   51200000LL   // NU*128 = 12.8M
#define OFF_H_I     64000000LL   // NI*256 = 51.2M
#define OFF_H_U     115200000LL  // NU*256 = 25.6M
#define OFF_Y_U2    140800000LL  // NU*128
#define OFF_Y_I2    153600000LL  // NI*128
#define OFF_AGG2_I  179200000LL  // NI*128
#define OFF_AGG2_U  204800000LL  // NU*128
#define SCRATCH_SZ  217600000LL

__device__ float g_scratch[SCRATCH_SZ];

// ---------------------------------------------------------------------------
// Fused GEMM: C[M,N] = A1[M,K]@W1[N,K]^T (+ A2@W2^T) (+ bias) (+ addend) [relu]
// Tile 128x128, BK=16, 256 threads, 8x8 per thread.
// ---------------------------------------------------------------------------
#define BM 128
#define BN 128
#define BK 16

__global__ void __launch_bounds__(256, 2) gemm_fused_kernel(
    const float* __restrict__ A1, const float* __restrict__ W1,
    const float* __restrict__ bias,
    const float* __restrict__ A2, const float* __restrict__ W2,
    const float* __restrict__ addend,
    float* __restrict__ C, int M, int N, int K, int do_relu)
{
    __shared__ float As[BK][BM];
    __shared__ float Ws[BK][BN];

    const int bm = blockIdx.y * BM;
    const int bn = blockIdx.x * BN;
    const int tid = threadIdx.x;
    const int tx = tid & 15;        // n
    const int ty = tid >> 4;        // m

    float acc[8][8];
#pragma unroll
    for (int i = 0; i < 8; i++)
#pragma unroll
        for (int j = 0; j < 8; j++) acc[i][j] = 0.0f;

    const int npass = (A2 != nullptr) ? 2 : 1;

    for (int pass = 0; pass < npass; pass++) {
        const float* __restrict__ A = pass ? A2 : A1;
        const float* __restrict__ W = pass ? W2 : W1;

        for (int k0 = 0; k0 < K; k0 += BK) {
#pragma unroll
            for (int i = 0; i < 2; i++) {
                int t   = tid + i * 256;
                int row = t >> 2;
                int c4  = (t & 3) * 4;
                float4 v = make_float4(0.f, 0.f, 0.f, 0.f);
                int gr = bm + row;
                if (gr < M)
                    v = *(const float4*)(A + (size_t)gr * K + k0 + c4);
                As[c4 + 0][row] = v.x;
                As[c4 + 1][row] = v.y;
                As[c4 + 2][row] = v.z;
                As[c4 + 3][row] = v.w;
            }
#pragma unroll
            for (int i = 0; i < 2; i++) {
                int t   = tid + i * 256;
                int row = t >> 2;
                int c4  = (t & 3) * 4;
                float4 v = *(const float4*)(W + (size_t)(bn + row) * K + k0 + c4);
                Ws[c4 + 0][row] = v.x;
                Ws[c4 + 1][row] = v.y;
                Ws[c4 + 2][row] = v.z;
                Ws[c4 + 3][row] = v.w;
            }
            __syncthreads();

#pragma unroll
            for (int k = 0; k < BK; k++) {
                float ra[8], rb[8];
                *(float4*)(ra)     = *(const float4*)&As[k][ty * 8];
                *(float4*)(ra + 4) = *(const float4*)&As[k][ty * 8 + 4];
                *(float4*)(rb)     = *(const float4*)&Ws[k][tx * 8];
                *(float4*)(rb + 4) = *(const float4*)&Ws[k][tx * 8 + 4];
#pragma unroll
                for (int i = 0; i < 8; i++)
#pragma unroll
                    for (int j = 0; j < 8; j++)
                        acc[i][j] += ra[i] * rb[j];
            }
            __syncthreads();
        }
    }

    float bv[8];
#pragma unroll
    for (int j = 0; j < 8; j++)
        bv[j] = bias ? bias[bn + tx * 8 + j] : 0.0f;

#pragma unroll
    for (int i = 0; i < 8; i++) {
        int gr = bm + ty * 8 + i;
        if (gr >= M) continue;
        size_t roff = (size_t)gr * N + bn + tx * 8;
        float* crow = C + roff;
#pragma unroll
        for (int j = 0; j < 8; j += 4) {
            float4 v;
            v.x = acc[i][j + 0] + bv[j + 0];
            v.y = acc[i][j + 1] + bv[j + 1];
            v.z = acc[i][j + 2] + bv[j + 2];
            v.w = acc[i][j + 3] + bv[j + 3];
            if (addend) {
                float4 a = *(const float4*)(addend + roff + j);
                v.x += a.x; v.y += a.y; v.z += a.z; v.w += a.w;
            }
            if (do_relu) {
                v.x = fmaxf(v.x, 0.f); v.y = fmaxf(v.y, 0.f);
                v.z = fmaxf(v.z, 0.f); v.w = fmaxf(v.w, 0.f);
            }
            *(float4*)(crow + j) = v;
        }
    }
}

// ---------------------------------------------------------------------------
// Edge scatter-add, F=128:  agg[sidx[e]] += x[gidx[e]]
// One thread per (edge, float4 chunk); vectorized red.global.add.v4.f32.
// ---------------------------------------------------------------------------
__global__ void __launch_bounds__(256) scatter_add128_kernel(
    const float* __restrict__ x,
    const int* __restrict__ gidx,
    const int* __restrict__ sidx,
    float* __restrict__ agg, int E)
{
    long long idx = (long long)blockIdx.x * blockDim.x + threadIdx.x;
    if (idx >= (long long)E * 32) return;
    int e = (int)(idx >> 5);
    int c = (int)(idx & 31) * 4;

    int g = __ldg(gidx + e);
    int s = __ldg(sidx + e);
    float4 v = *(const float4*)(x + (size_t)g * 128 + c);
    float* p = agg + (size_t)s * 128 + c;
    asm volatile("red.global.add.v4.f32 [%0], {%1, %2, %3, %4};"
                 :: "l"(p), "f"(v.x), "f"(v.y), "f"(v.z), "f"(v.w)
                 : "memory");
}

// ---------------------------------------------------------------------------

static inline dim3 gemm_grid(int M, int N) {
    return dim3(N / 128, (M + 127) / 128);
}

extern "C" void kernel_launch(void* const* d_in, const int* in_sizes, int n_in,
                              void* d_out, int out_size)
{
    const float* x_user       = (const float*)d_in[0];
    const float* x_issue      = (const float*)d_in[1];
    const float* W_mlp        = (const float*)d_in[2];
    const float* b_mlp        = (const float*)d_in[3];
    const float* c1_ui_rel_W  = (const float*)d_in[4];
    const float* c1_ui_rel_b  = (const float*)d_in[5];
    const float* c1_ui_root_W = (const float*)d_in[6];
    const float* c1_iu_rel_W  = (const float*)d_in[7];
    const float* c1_iu_rel_b  = (const float*)d_in[8];
    const float* c1_iu_root_W = (const float*)d_in[9];
    const float* c2_ui_rel_W  = (const float*)d_in[10];
    const float* c2_ui_rel_b  = (const float*)d_in[11];
    const float* c2_ui_root_W = (const float*)d_in[12];
    const float* c2_iu_rel_W  = (const float*)d_in[13];
    const float* c2_iu_rel_b  = (const float*)d_in[14];
    const float* c2_iu_root_W = (const float*)d_in[15];
    const int*   src          = (const int*)d_in[16];
    const int*   dst          = (const int*)d_in[17];

    float* out       = (float*)d_out;
    float* out_issue = out;
    float* out_user  = out + (size_t)NI * DOUT;

    float* S = nullptr;
    cudaGetSymbolAddress((void**)&S, g_scratch);
    float* xi     = S + OFF_XI;
    float* agg_i  = S + OFF_AGG_I;
    float* agg_u  = S + OFF_AGG_U;
    float* h_i    = S + OFF_H_I;
    float* h_u    = S + OFF_H_U;
    float* y_u2   = S + OFF_Y_U2;
    float* y_i2   = S + OFF_Y_I2;
    float* agg2_i = S + OFF_AGG2_I;
    float* agg2_u = S + OFF_AGG2_U;

    // zero aggregation buffers (all 128-dim now)
    cudaMemsetAsync(agg_i,  0, (size_t)NI * DIN * sizeof(float), 0);
    cudaMemsetAsync(agg_u,  0, (size_t)NU * DIN * sizeof(float), 0);
    cudaMemsetAsync(agg2_i, 0, (size_t)NI * DIN * sizeof(float), 0);
    cudaMemsetAsync(agg2_u, 0, (size_t)NU * DIN * sizeof(float), 0);

    dim3 blk(256);
    const int snb = (int)(((long long)NE * 32 + 255) / 256);

    // xi = x_issue @ W_mlp^T + b_mlp
    gemm_fused_kernel<<<gemm_grid(NI, DIN), blk>>>(
        x_issue, W_mlp, b_mlp, nullptr, nullptr, nullptr, xi, NI, DIN, DIN, 0);

    // conv1 scatters (F=128)
    scatter_add128_kernel<<<snb, blk>>>(x_user, src, dst, agg_i, NE);
    scatter_add128_kernel<<<snb, blk>>>(xi,     dst, src, agg_u, NE);

    // h_i = relu(agg_i@c1_ui_rel^T + b + xi@c1_ui_root^T)
    gemm_fused_kernel<<<gemm_grid(NI, DHID), blk>>>(
        agg_i, c1_ui_rel_W, c1_ui_rel_b, xi, c1_ui_root_W, nullptr,
        h_i, NI, DHID, DIN, 1);
    // h_u = relu(agg_u@c1_iu_rel^T + b + x_user@c1_iu_root^T)
    gemm_fused_kernel<<<gemm_grid(NU, DHID), blk>>>(
        agg_u, c1_iu_rel_W, c1_iu_rel_b, x_user, c1_iu_root_W, nullptr,
        h_u, NU, DHID, DIN, 1);

    // conv2: transform-before-scatter
    // y_u2 = h_u @ c2_ui_rel^T   (no bias — bias added once per dst row later)
    gemm_fused_kernel<<<gemm_grid(NU, DOUT), blk>>>(
        h_u, c2_ui_rel_W, nullptr, nullptr, nullptr, nullptr,
        y_u2, NU, DOUT, DHID, 0);
    // y_i2 = h_i @ c2_iu_rel^T
    gemm_fused_kernel<<<gemm_grid(NI, DOUT), blk>>>(
        h_i, c2_iu_rel_W, nullptr, nullptr, nullptr, nullptr,
        y_i2, NI, DOUT, DHID, 0);

    // conv2 scatters (F=128)
    scatter_add128_kernel<<<snb, blk>>>(y_u2, src, dst, agg2_i, NE);
    scatter_add128_kernel<<<snb, blk>>>(y_i2, dst, src, agg2_u, NE);

    // out_issue = h_i@c2_ui_root^T + c2_ui_rel_b + agg2_i
    gemm_fused_kernel<<<gemm_grid(NI, DOUT), blk>>>(
        h_i, c2_ui_root_W, c2_ui_rel_b, nullptr, nullptr, agg2_i,
        out_issue, NI, DOUT, DHID, 0);
    // out_user = h_u@c2_iu_root^T + c2_iu_rel_b + agg2_u
    gemm_fused_kernel<<<gemm_grid(NU, DOUT), blk>>>(
        h_u, c2_iu_root_W, c2_iu_rel_b, nullptr, nullptr, agg2_u,
        out_user, NU, DOUT, DHID, 0);
}

// round 10
// speedup vs baseline: 2.4824x; 1.8874x over previous
#include <cuda_runtime.h>
#include <cuda_bf16.h>
#include <cstdint>

// ---------------------------------------------------------------------------
// HeteroGraphSAGE forward on GB300 — round 4: mma.sync bf16 tensor cores
// (hi/lo split x3 products, fp32 accumulate in registers).
// tcgen05 is unavailable: harness PTX target is sm_103 (no 'a' features).
// ---------------------------------------------------------------------------

#define NU   100000
#define NI   200000
#define NE   600000
#define DIN  128
#define DHID 256
#define DOUT 128

// scratch layout (floats)
#define OFF_XI      0LL
#define OFF_AGG_I   25600000LL
#define OFF_AGG_U   51200000LL
#define OFF_H_I     64000000LL
#define OFF_H_U     115200000LL
#define OFF_Y_U2    140800000LL
#define OFF_Y_I2    153600000LL
#define OFF_AGG2_I  179200000LL
#define OFF_AGG2_U  204800000LL
#define SCRATCH_SZ  217600000LL

__device__ float g_scratch[SCRATCH_SZ];

// ---------------------------------------------------------------------------
// helpers
// ---------------------------------------------------------------------------
__device__ __forceinline__ uint32_t smem_u32(const void* p) {
    uint32_t a;
    asm("{ .reg .u64 t; cvta.to.shared.u64 t, %1; cvt.u32.u64 %0, t; }"
        : "=r"(a) : "l"(p));
    return a;
}

__device__ __forceinline__ void ldsm4(uint32_t* r, uint32_t addr) {
    asm volatile("ldmatrix.sync.aligned.m8n8.x4.shared.b16 {%0,%1,%2,%3}, [%4];"
                 : "=r"(r[0]), "=r"(r[1]), "=r"(r[2]), "=r"(r[3])
                 : "r"(addr));
}

__device__ __forceinline__ void mma_bf16(float* c, const uint32_t* a,
                                         const uint32_t* b) {
    asm volatile(
        "mma.sync.aligned.m16n8k16.row.col.f32.bf16.bf16.f32 "
        "{%0,%1,%2,%3}, {%4,%5,%6,%7}, {%8,%9}, {%0,%1,%2,%3};"
        : "+f"(c[0]), "+f"(c[1]), "+f"(c[2]), "+f"(c[3])
        : "r"(a[0]), "r"(a[1]), "r"(a[2]), "r"(a[3]),
          "r"(b[0]), "r"(b[1]));
}

// split fp32x4 -> bf16 hi x4 (8B) + lo x4 (8B)
__device__ __forceinline__ void split_store(__nv_bfloat16* hi_p,
                                            __nv_bfloat16* lo_p, float4 v) {
    __nv_bfloat162 h0 = __floats2bfloat162_rn(v.x, v.y);
    __nv_bfloat162 h1 = __floats2bfloat162_rn(v.z, v.w);
    float2 f0 = __bfloat1622float2(h0);
    float2 f1 = __bfloat1622float2(h1);
    __nv_bfloat162 l0 = __floats2bfloat162_rn(v.x - f0.x, v.y - f0.y);
    __nv_bfloat162 l1 = __floats2bfloat162_rn(v.z - f1.x, v.w - f1.y);
    uint2 hu, lu;
    hu.x = *(uint32_t*)&h0; hu.y = *(uint32_t*)&h1;
    lu.x = *(uint32_t*)&l0; lu.y = *(uint32_t*)&l1;
    *(uint2*)hi_p = hu;
    *(uint2*)lo_p = lu;
}

// ---------------------------------------------------------------------------
// Tensor-core fused GEMM (mma.sync bf16, split-3):
//   C[M,N] = A1[M,K]@W1[N,K]^T (+ A2@W2^T) (+ bias) (+ addend) [relu]
// CTA tile 128x128, BK=32 fp32 k per chunk. 8 warps: 4(m) x 2(n),
// warp tile 32x64. Smem pitch 40 bf16 (80B) -> conflict-free ldmatrix.
// ---------------------------------------------------------------------------
#define LDT 40

__global__ void __launch_bounds__(256, 2) gemm_mma_kernel(
    const float* __restrict__ A1, const float* __restrict__ W1,
    const float* __restrict__ bias,
    const float* __restrict__ A2, const float* __restrict__ W2,
    const float* __restrict__ addend,
    float* __restrict__ C, int M, int N, int K, int do_relu)
{
    __shared__ __align__(16) __nv_bfloat16 Ah[128][LDT];
    __shared__ __align__(16) __nv_bfloat16 Al[128][LDT];
    __shared__ __align__(16) __nv_bfloat16 Bh[128][LDT];
    __shared__ __align__(16) __nv_bfloat16 Bl[128][LDT];

    const int tid    = threadIdx.x;
    const int lane   = tid & 31;
    const int wid    = tid >> 5;
    const int warp_m = wid & 3;     // 0..3 -> 32 rows each
    const int warp_n = wid >> 2;    // 0..1 -> 64 cols each
    const int bm     = blockIdx.x * 128;
    const int bn     = blockIdx.y * 128;

    const uint32_t sAh = smem_u32(Ah);
    const uint32_t sAl = smem_u32(Al);
    const uint32_t sBh = smem_u32(Bh);
    const uint32_t sBl = smem_u32(Bl);

    float acc[2][8][4];
#pragma unroll
    for (int f = 0; f < 2; f++)
#pragma unroll
        for (int j = 0; j < 8; j++)
#pragma unroll
            for (int q = 0; q < 4; q++) acc[f][j][q] = 0.0f;

    // per-lane ldmatrix offsets (element units within a row handled below)
    // A frag: row = mbase + (lane & 15), col = ks + (lane >> 4) * 8
    // B frag: row = nbase + (lane & 7) + ((lane >> 4) & 1) * 8,
    //         col = ks + ((lane >> 3) & 1) * 8
    const int a_r = lane & 15;
    const int a_c = (lane >> 4) * 8;
    const int b_r = (lane & 7) + ((lane >> 4) & 1) * 8;
    const int b_c = ((lane >> 3) & 1) * 8;

    const int npass = (A2 != nullptr) ? 2 : 1;

    for (int pass = 0; pass < npass; pass++) {
        const float* __restrict__ A = pass ? A2 : A1;
        const float* __restrict__ W = pass ? W2 : W1;

        for (int k0 = 0; k0 < K; k0 += 32) {
            // ---- build A tile: 128 rows x 32 fp32 -> hi/lo bf16 ----
#pragma unroll
            for (int i = 0; i < 4; i++) {
                int u  = tid + i * 256;       // 0..1023
                int m  = u >> 3;
                int k4 = (u & 7) * 4;
                float4 v = make_float4(0.f, 0.f, 0.f, 0.f);
                int gr = bm + m;
                if (gr < M)
                    v = *(const float4*)(A + (size_t)gr * K + k0 + k4);
                split_store(&Ah[m][k4], &Al[m][k4], v);
            }
            // ---- build B tile: 128 n-rows x 32 fp32 ----
#pragma unroll
            for (int i = 0; i < 4; i++) {
                int u  = tid + i * 256;
                int n  = u >> 3;
                int k4 = (u & 7) * 4;
                float4 v = *(const float4*)(W + (size_t)(bn + n) * K + k0 + k4);
                split_store(&Bh[n][k4], &Bl[n][k4], v);
            }
            __syncthreads();

#pragma unroll
            for (int ks = 0; ks < 32; ks += 16) {
                uint32_t ah[8], bx[16];

                // A-hi frags (2 x m16)
#pragma unroll
                for (int f = 0; f < 2; f++) {
                    int row = warp_m * 32 + f * 16 + a_r;
                    ldsm4(&ah[4 * f],
                          sAh + (uint32_t)(row * LDT + ks + a_c) * 2);
                }
                // B-hi frags (4 x n16 covering 64 cols)
#pragma unroll
                for (int g = 0; g < 4; g++) {
                    int row = warp_n * 64 + g * 16 + b_r;
                    ldsm4(&bx[4 * g],
                          sBh + (uint32_t)(row * LDT + ks + b_c) * 2);
                }
                // hh
#pragma unroll
                for (int f = 0; f < 2; f++)
#pragma unroll
                    for (int j = 0; j < 8; j++)
                        mma_bf16(acc[f][j], &ah[4 * f], &bx[2 * j]);

                // A-lo frags -> lh (al x bh)
                {
                    uint32_t al[8];
#pragma unroll
                    for (int f = 0; f < 2; f++) {
                        int row = warp_m * 32 + f * 16 + a_r;
                        ldsm4(&al[4 * f],
                              sAl + (uint32_t)(row * LDT + ks + a_c) * 2);
                    }
#pragma unroll
                    for (int f = 0; f < 2; f++)
#pragma unroll
                        for (int j = 0; j < 8; j++)
                            mma_bf16(acc[f][j], &al[4 * f], &bx[2 * j]);
                }
                // B-lo frags (overwrite bx) -> hl (ah x bl)
#pragma unroll
                for (int g = 0; g < 4; g++) {
                    int row = warp_n * 64 + g * 16 + b_r;
                    ldsm4(&bx[4 * g],
                          sBl + (uint32_t)(row * LDT + ks + b_c) * 2);
                }
#pragma unroll
                for (int f = 0; f < 2; f++)
#pragma unroll
                    for (int j = 0; j < 8; j++)
                        mma_bf16(acc[f][j], &ah[4 * f], &bx[2 * j]);
            }
            __syncthreads();
        }
    }

    // ---- epilogue ----
#pragma unroll
    for (int f = 0; f < 2; f++) {
        int r0 = warp_m * 32 + f * 16 + (lane >> 2);
#pragma unroll
        for (int half = 0; half < 2; half++) {
            int gr = bm + r0 + half * 8;
            if (gr >= M) continue;
            float* crow = C + (size_t)gr * N;
            const float* arow = addend ? addend + (size_t)gr * N : nullptr;
#pragma unroll
            for (int j = 0; j < 8; j++) {
                int col = bn + warp_n * 64 + j * 8 + (lane & 3) * 2;
                float2 v;
                v.x = acc[f][j][half * 2 + 0];
                v.y = acc[f][j][half * 2 + 1];
                if (bias) {
                    float2 b = *(const float2*)(bias + col);
                    v.x += b.x; v.y += b.y;
                }
                if (arow) {
                    float2 a = *(const float2*)(arow + col);
                    v.x += a.x; v.y += a.y;
                }
                if (do_relu) {
                    v.x = fmaxf(v.x, 0.f);
                    v.y = fmaxf(v.y, 0.f);
                }
                *(float2*)(crow + col) = v;
            }
        }
    }
}

// ---------------------------------------------------------------------------
// Edge scatter-add, F=128:  agg[sidx[e]] += x[gidx[e]]  (red.global.add.v4)
// ---------------------------------------------------------------------------
__global__ void __launch_bounds__(256) scatter_add128_kernel(
    const float* __restrict__ x,
    const int* __restrict__ gidx,
    const int* __restrict__ sidx,
    float* __restrict__ agg, int E)
{
    long long idx = (long long)blockIdx.x * blockDim.x + threadIdx.x;
    if (idx >= (long long)E * 32) return;
    int e = (int)(idx >> 5);
    int c = (int)(idx & 31) * 4;

    int g = __ldg(gidx + e);
    int s = __ldg(sidx + e);
    float4 v = *(const float4*)(x + (size_t)g * 128 + c);
    float* p = agg + (size_t)s * 128 + c;
    asm volatile("red.global.add.v4.f32 [%0], {%1, %2, %3, %4};"
                 :: "l"(p), "f"(v.x), "f"(v.y), "f"(v.z), "f"(v.w)
                 : "memory");
}

// ---------------------------------------------------------------------------

extern "C" void kernel_launch(void* const* d_in, const int* in_sizes, int n_in,
                              void* d_out, int out_size)
{
    const float* x_user       = (const float*)d_in[0];
    const float* x_issue      = (const float*)d_in[1];
    const float* W_mlp        = (const float*)d_in[2];
    const float* b_mlp        = (const float*)d_in[3];
    const float* c1_ui_rel_W  = (const float*)d_in[4];
    const float* c1_ui_rel_b  = (const float*)d_in[5];
    const float* c1_ui_root_W = (const float*)d_in[6];
    const float* c1_iu_rel_W  = (const float*)d_in[7];
    const float* c1_iu_rel_b  = (const float*)d_in[8];
    const float* c1_iu_root_W = (const float*)d_in[9];
    const float* c2_ui_rel_W  = (const float*)d_in[10];
    const float* c2_ui_rel_b  = (const float*)d_in[11];
    const float* c2_ui_root_W = (const float*)d_in[12];
    const float* c2_iu_rel_W  = (const float*)d_in[13];
    const float* c2_iu_rel_b  = (const float*)d_in[14];
    const float* c2_iu_root_W = (const float*)d_in[15];
    const int*   src          = (const int*)d_in[16];
    const int*   dst          = (const int*)d_in[17];

    float* out       = (float*)d_out;
    float* out_issue = out;
    float* out_user  = out + (size_t)NI * DOUT;

    float* S = nullptr;
    cudaGetSymbolAddress((void**)&S, g_scratch);
    float* xi     = S + OFF_XI;
    float* agg_i  = S + OFF_AGG_I;
    float* agg_u  = S + OFF_AGG_U;
    float* h_i    = S + OFF_H_I;
    float* h_u    = S + OFF_H_U;
    float* y_u2   = S + OFF_Y_U2;
    float* y_i2   = S + OFF_Y_I2;
    float* agg2_i = S + OFF_AGG2_I;
    float* agg2_u = S + OFF_AGG2_U;

    // zero aggregation buffers
    cudaMemsetAsync(agg_i,  0, (size_t)NI * DIN * sizeof(float), 0);
    cudaMemsetAsync(agg_u,  0, (size_t)NU * DIN * sizeof(float), 0);
    cudaMemsetAsync(agg2_i, 0, (size_t)NI * DIN * sizeof(float), 0);
    cudaMemsetAsync(agg2_u, 0, (size_t)NU * DIN * sizeof(float), 0);

    dim3 blk(256);
    const int snb = (int)(((long long)NE * 32 + 255) / 256);
    const int gNI = (NI + 127) / 128;
    const int gNU = (NU + 127) / 128;

    // xi = x_issue @ W_mlp^T + b_mlp      (M=NI, N=128, K=128)
    gemm_mma_kernel<<<dim3(gNI, 1), blk>>>(
        x_issue, W_mlp, b_mlp, nullptr, nullptr, nullptr,
        xi, NI, DIN, DIN, 0);

    // conv1 scatters (F=128)
    scatter_add128_kernel<<<snb, blk>>>(x_user, src, dst, agg_i, NE);
    scatter_add128_kernel<<<snb, blk>>>(xi,     dst, src, agg_u, NE);

    // h_i = relu(agg_i@c1_ui_rel^T + b + xi@c1_ui_root^T)  (N=256, K=128 x2)
    gemm_mma_kernel<<<dim3(gNI, 2), blk>>>(
        agg_i, c1_ui_rel_W, c1_ui_rel_b, xi, c1_ui_root_W, nullptr,
        h_i, NI, DHID, DIN, 1);
    // h_u = relu(agg_u@c1_iu_rel^T + b + x_user@c1_iu_root^T)
    gemm_mma_kernel<<<dim3(gNU, 2), blk>>>(
        agg_u, c1_iu_rel_W, c1_iu_rel_b, x_user, c1_iu_root_W, nullptr,
        h_u, NU, DHID, DIN, 1);

    // conv2: transform-before-scatter (N=128, K=256)
    gemm_mma_kernel<<<dim3(gNU, 1), blk>>>(
        h_u, c2_ui_rel_W, nullptr, nullptr, nullptr, nullptr,
        y_u2, NU, DOUT, DHID, 0);
    gemm_mma_kernel<<<dim3(gNI, 1), blk>>>(
        h_i, c2_iu_rel_W, nullptr, nullptr, nullptr, nullptr,
        y_i2, NI, DOUT, DHID, 0);

    // conv2 scatters (F=128)
    scatter_add128_kernel<<<snb, blk>>>(y_u2, src, dst, agg2_i, NE);
    scatter_add128_kernel<<<snb, blk>>>(y_i2, dst, src, agg2_u, NE);

    // out_issue = h_i@c2_ui_root^T + c2_ui_rel_b + agg2_i
    gemm_mma_kernel<<<dim3(gNI, 1), blk>>>(
        h_i, c2_ui_root_W, c2_ui_rel_b, nullptr, nullptr, agg2_i,
        out_issue, NI, DOUT, DHID, 0);
    // out_user = h_u@c2_iu_root^T + c2_iu_rel_b + agg2_u
    gemm_mma_kernel<<<dim3(gNU, 1), blk>>>(
        h_u, c2_iu_root_W, c2_iu_rel_b, nullptr, nullptr, agg2_u,
        out_user, NU, DOUT, DHID, 0);
}